// round 4
// baseline (speedup 1.0000x reference)
#include <cuda_runtime.h>
#include <math.h>

// GraphTemporalRefiner — folded operators + last-block fused tail.
//   xg = conv7(x);  w[b,n,:] = xl[b]^T W2_n + wb_n   (W2 = Qp_n^T Kp_n/sqrt(HD))
//   scores[b,n,t] = w[b,n] . xg[b,t]  (const cancels in softmax)
//   u[b,n] = softmax-weighted sum_t xg[b,t]
//   a[b]   = C u[b] + ab   (C folds Wv, theta, out_proj);  LN -> gelu MLP -> out
// Launch 1 (pre): fold all weights (W2, wb, C, ab), reset batch counters.
// Launch 2 (score): 512 blocks = 16 T-slices x 32 batches; fused conv, scores,
// split-softmax partials; the LAST slice block of each batch runs the tail.

namespace {
constexpr int Bn  = 32;
constexpr int Tn  = 1024;
constexpr int Dn  = 64;
constexpr int Hn  = 128;
constexpr int NHn = 4;
constexpr int SL  = 64;
constexpr int NS  = Tn / SL;    // 16
}

__device__ float g_W2[NHn * Dn * Dn];     // (n, e, d)
__device__ float g_wb[NHn * Dn];
__device__ float g_C[Hn * NHn * Dn];      // (i, n*64+d)
__device__ float g_ab[Hn];
__device__ float g_m[Bn * NHn * NS];
__device__ float g_l[Bn * NHn * NS];
__device__ float g_u[Bn * NHn * NS * Dn];
__device__ unsigned int g_cnt[Bn];

// ---------------------------------------------------------------------------
// pre: blocks 0..3 -> W2_n, wb_n;  blocks 4..11 -> C rows (16 each), ab.
// ---------------------------------------------------------------------------
__global__ void __launch_bounds__(256) pre_kernel(
    const float* __restrict__ theta_w,    // (128, 64)
    const float* __restrict__ theta_b,    // (128)
    const float* __restrict__ in_proj_w,  // (384, 128)
    const float* __restrict__ in_proj_b,  // (384)
    const float* __restrict__ out_proj_w, // (128, 128)
    const float* __restrict__ out_proj_b) // (128)
{
    const int tid = threadIdx.x;
    const float SCALE = 0.17677669529663687f;   // 1/sqrt(32)

    if (blockIdx.x < 4) {
        const int n = blockIdx.x;
        __shared__ float Qp[32 * Dn];   // 8 KB
        __shared__ float Kp[32 * Dn];   // 8 KB
        __shared__ float qb[32];

        // Qp[j][e] = Wq_n[j] . theta[:,e] ; Kp likewise (Wk rows offset 128)
#pragma unroll
        for (int k = 0; k < 8; k++) {
            int o = tid + k * 256;      // 2048 = 32*64
            int j = o >> 6, e = o & 63;
            float aq = 0.f, ak = 0.f;
#pragma unroll 8
            for (int c = 0; c < Hn; c++) {
                float th = __ldg(&theta_w[c * Dn + e]);
                aq += __ldg(&in_proj_w[(n * 32 + j) * Hn + c]) * th;
                ak += __ldg(&in_proj_w[(Hn + n * 32 + j) * Hn + c]) * th;
            }
            Qp[j * Dn + e] = aq;
            Kp[j * Dn + e] = ak;
        }
        if (tid < 32) {
            float acc = in_proj_b[n * 32 + tid];
#pragma unroll 8
            for (int c = 0; c < Hn; c++)
                acc += __ldg(&in_proj_w[(n * 32 + tid) * Hn + c]) * theta_b[c];
            qb[tid] = acc;
        }
        __syncthreads();

        // W2[e][d] = sum_j Qp[j][e] Kp[j][d] * SCALE
#pragma unroll
        for (int k = 0; k < 16; k++) {
            int o = tid + k * 256;      // 4096 = 64*64
            int e = o >> 6, d = o & 63;
            float acc = 0.f;
#pragma unroll 8
            for (int j = 0; j < 32; j++) acc += Qp[j * Dn + e] * Kp[j * Dn + d];
            g_W2[(n * Dn + e) * Dn + d] = acc * SCALE;
        }
        if (tid < Dn) {
            float acc = 0.f;
#pragma unroll 8
            for (int j = 0; j < 32; j++) acc += qb[j] * Kp[j * Dn + tid];
            g_wb[n * Dn + tid] = acc * SCALE;
        }
    } else {
        const int chunk = blockIdx.x - 4;     // C rows i = chunk*16 .. +15
        __shared__ float Vp[Hn * Dn];   // 32 KB
        __shared__ float vb[Hn];

        if (blockIdx.x == 4 && tid < Bn) g_cnt[tid] = 0u;

        // Vp[h][d] = Wv[h] . theta[:,d]  (Wv rows offset 256)
#pragma unroll
        for (int k = 0; k < 32; k++) {
            int o = tid + k * 256;      // 8192 = 128*64
            int h = o >> 6, d = o & 63;
            float acc = 0.f;
#pragma unroll 8
            for (int c = 0; c < Hn; c++)
                acc += __ldg(&in_proj_w[(2 * Hn + h) * Hn + c]) *
                       __ldg(&theta_w[c * Dn + d]);
            Vp[h * Dn + d] = acc;
        }
        if (tid < Hn) {
            float acc = in_proj_b[2 * Hn + tid];
#pragma unroll 8
            for (int c = 0; c < Hn; c++)
                acc += __ldg(&in_proj_w[(2 * Hn + tid) * Hn + c]) * theta_b[c];
            vb[tid] = acc;
        }
        __syncthreads();

        // C[i][n*64+d] = sum_j OP[i, n*32+j] Vp[n*32+j][d]
#pragma unroll
        for (int k = 0; k < 16; k++) {
            int o = tid + k * 256;      // 4096 = 16*256
            int il = o >> 8, nd = o & 255;
            int n = nd >> 6, d = nd & 63;
            int i = chunk * 16 + il;
            float acc = 0.f;
#pragma unroll 8
            for (int j = 0; j < 32; j++)
                acc += __ldg(&out_proj_w[i * Hn + n * 32 + j]) *
                       Vp[(n * 32 + j) * Dn + d];
            g_C[i * (NHn * Dn) + nd] = acc;
        }
        if (tid < 16) {
            int i = chunk * 16 + tid;
            float acc = out_proj_b[i];
#pragma unroll 8
            for (int h = 0; h < Hn; h++)
                acc += __ldg(&out_proj_w[i * Hn + h]) * vb[h];
            g_ab[i] = acc;
        }
    }
}

// ---------------------------------------------------------------------------
// score: grid (NS, Bn). Fused conv, per-head scores, slice softmax partials.
// Last block per batch runs the full tail inline.
// ---------------------------------------------------------------------------
__global__ void __launch_bounds__(256) score_kernel(
    const float* __restrict__ x,
    const float* __restrict__ ln_g,
    const float* __restrict__ ln_b,
    const float* __restrict__ w1,
    const float* __restrict__ b1,
    const float* __restrict__ w2,
    const float* __restrict__ b2,
    float* __restrict__ out)
{
    const int s = blockIdx.x, b = blockIdx.y, tid = threadIdx.x;
    const int warp = tid >> 5, lane = tid & 31;
    const int t0 = s * SL;

    __shared__ float xr[(SL + 6) * Dn];   // raw x rows [t0-3, t0+SL+2]  17.5 KB
    __shared__ float xg[SL][Dn + 1];      // conv output                16.25 KB
    __shared__ float sc[NHn][SL];
    __shared__ float sw[NHn][Dn];
    __shared__ float sxl[Dn];
    __shared__ float s_ML[NHn][2];
    __shared__ float s_u[NHn * Dn];
    __shared__ float s_a[Hn];
    __shared__ float s_hid[Hn];
    __shared__ float s_mv[2];
    __shared__ int   s_last;

    // stage raw x rows (float4, coalesced); OOB rows left unread
    {
        const float4* xb4 = (const float4*)&x[(size_t)b * Tn * Dn];
        float4* xr4 = (float4*)xr;
        for (int i = tid; i < (SL + 6) * 16; i += 256) {
            int r = i >> 4, gt = t0 - 3 + r;
            if (gt >= 0 && gt < Tn) xr4[i] = __ldg(&xb4[gt * 16 + (i & 15)]);
        }
    }

    // xl = conv at t = T-1 (only backward taps exist)
    if (tid < Dn) {
        float sum = 0.f, ws = 0.f;
#pragma unroll
        for (int dd = 0; dd < 4; dd++) {
            float wv = 1.0f / (1.0f + (float)dd);
            ws += wv;
            sum += wv * __ldg(&x[((size_t)b * Tn + (Tn - 1 - dd)) * Dn + tid]);
        }
        sxl[tid] = sum / ws;
    }

    // w[n][d] = wb + xl^T W2_n  (coalesced over d)
    {
        int n = tid >> 6, d = tid & 63;
        float acc = __ldg(&g_wb[tid]);
#pragma unroll 8
        for (int k = 0; k < Dn; k++)
            acc += sxl[k] * __ldg(&g_W2[(n * Dn + k) * Dn + d]);
        // sxl not ready yet -> need sync before this; moved below
        sw[n][d] = acc;
    }
    // NOTE: the loop above uses sxl; ensure ordering with a sync *before* it.
    __syncthreads();   // (conservative: xr + sxl ready for everything below)

    // recompute w correctly now that sxl is guaranteed visible
    {
        int n = tid >> 6, d = tid & 63;
        float acc = __ldg(&g_wb[tid]);
#pragma unroll 8
        for (int k = 0; k < Dn; k++)
            acc += sxl[k] * __ldg(&g_W2[(n * Dn + k) * Dn + d]);
        sw[n][d] = acc;
    }

    // conv from smem: xg[tl][d]
    for (int o = tid; o < SL * Dn; o += 256) {
        int tl = o >> 6, d = o & 63, t = t0 + tl;
        float sum = 0.f, ws = 0.f;
#pragma unroll
        for (int dd = -3; dd <= 3; dd++) {
            int tt = t + dd;
            if (tt >= 0 && tt < Tn) {
                float wv = 1.0f / (1.0f + (float)(dd < 0 ? -dd : dd));
                ws += wv;
                sum += wv * xr[(tl + 3 + dd) * Dn + d];
            }
        }
        xg[tl][d] = sum / ws;
    }
    __syncthreads();

    // scores: one per thread (n, tl)
    {
        int n = tid >> 6, tl = tid & 63;
        float acc = 0.f;
#pragma unroll 8
        for (int d = 0; d < Dn; d++) acc += sw[n][d] * xg[tl][d];
        sc[n][tl] = acc;
    }
    __syncthreads();

    // slice softmax partials: warp n = head n (64 elems)
    if (tid < NHn * 32) {
        int n = tid >> 5;
        float v0 = sc[n][lane], v1 = sc[n][lane + 32];
        float m = fmaxf(v0, v1);
#pragma unroll
        for (int off = 16; off; off >>= 1)
            m = fmaxf(m, __shfl_xor_sync(0xFFFFFFFFu, m, off));
        float e0 = expf(v0 - m), e1 = expf(v1 - m);
        sc[n][lane] = e0; sc[n][lane + 32] = e1;
        float l = e0 + e1;
#pragma unroll
        for (int off = 16; off; off >>= 1)
            l += __shfl_xor_sync(0xFFFFFFFFu, l, off);
        if (lane == 0) {
            g_m[(b * NHn + n) * NS + s] = m;
            g_l[(b * NHn + n) * NS + s] = l;
        }
    }
    __syncthreads();

    // slice u partial
    {
        int n = tid >> 6, d = tid & 63;
        float acc = 0.f;
#pragma unroll 4
        for (int t = 0; t < SL; t++) acc += sc[n][t] * xg[t][d];
        g_u[((b * NHn + n) * NS + s) * Dn + d] = acc;
    }

    // ---- last-block election --------------------------------------------
    __threadfence();
    __syncthreads();
    if (tid == 0) {
        unsigned int old = atomicAdd(&g_cnt[b], 1u);
        s_last = (old == NS - 1) ? 1 : 0;
    }
    __syncthreads();
    if (!s_last) return;
    __threadfence();   // acquire: other blocks' g_m/g_l/g_u now visible

    // ---- tail for batch b -------------------------------------------------
    if (tid < NHn) {
        float M = -1e30f;
#pragma unroll
        for (int k = 0; k < NS; k++) M = fmaxf(M, g_m[(b * NHn + tid) * NS + k]);
        float L = 0.f;
#pragma unroll
        for (int k = 0; k < NS; k++)
            L += g_l[(b * NHn + tid) * NS + k] *
                 expf(g_m[(b * NHn + tid) * NS + k] - M);
        s_ML[tid][0] = M;
        s_ML[tid][1] = L;
    }
    __syncthreads();
    {
        int n = tid >> 6, d = tid & 63;
        float acc = 0.f;
#pragma unroll
        for (int k = 0; k < NS; k++)
            acc += g_u[((b * NHn + n) * NS + k) * Dn + d] *
                   expf(g_m[(b * NHn + n) * NS + k] - s_ML[n][0]);
        s_u[n * Dn + d] = acc / s_ML[n][1];
    }
    __syncthreads();

    // a[i] = ab[i] + C[i] . u  — warp per output
#pragma unroll
    for (int k = 0; k < 16; k++) {
        int i = warp + 8 * k;
        float acc = 0.f;
#pragma unroll
        for (int m = 0; m < 8; m++)
            acc += __ldg(&g_C[i * 256 + lane + 32 * m]) * s_u[lane + 32 * m];
#pragma unroll
        for (int off = 16; off; off >>= 1)
            acc += __shfl_xor_sync(0xFFFFFFFFu, acc, off);
        if (lane == 0) s_a[i] = acc + g_ab[i];
    }
    __syncthreads();

    // LayerNorm over 128
    if (tid < 32) {
        float sum = s_a[tid] + s_a[tid + 32] + s_a[tid + 64] + s_a[tid + 96];
#pragma unroll
        for (int off = 16; off; off >>= 1)
            sum += __shfl_xor_sync(0xFFFFFFFFu, sum, off);
        if (tid == 0) s_mv[0] = sum * (1.0f / Hn);
    }
    __syncthreads();
    if (tid < 32) {
        float mu = s_mv[0], sum = 0.f;
#pragma unroll
        for (int k = 0; k < 4; k++) {
            float d = s_a[tid + 32 * k] - mu;
            sum += d * d;
        }
#pragma unroll
        for (int off = 16; off; off >>= 1)
            sum += __shfl_xor_sync(0xFFFFFFFFu, sum, off);
        if (tid == 0) s_mv[1] = sum * (1.0f / Hn);
    }
    __syncthreads();
    if (tid < Hn) {
        float inv = rsqrtf(s_mv[1] + 1e-5f);
        s_a[tid] = (s_a[tid] - s_mv[0]) * inv * ln_g[tid] + ln_b[tid];
    }
    __syncthreads();

    // hid = gelu(w1 @ ln + b1)
#pragma unroll
    for (int k = 0; k < 16; k++) {
        int i = warp + 8 * k;
        float acc = 0.f;
#pragma unroll
        for (int m = 0; m < 4; m++)
            acc += __ldg(&w1[i * Hn + lane + 32 * m]) * s_a[lane + 32 * m];
#pragma unroll
        for (int off = 16; off; off >>= 1)
            acc += __shfl_xor_sync(0xFFFFFFFFu, acc, off);
        if (lane == 0) {
            float v = acc + b1[i];
            s_hid[i] = 0.5f * v * (1.0f + erff(v * 0.70710678118654752f));
        }
    }
    __syncthreads();

    if (warp < 2) {
        float acc = 0.f;
#pragma unroll
        for (int m = 0; m < 4; m++)
            acc += __ldg(&w2[warp * Hn + lane + 32 * m]) * s_hid[lane + 32 * m];
#pragma unroll
        for (int off = 16; off; off >>= 1)
            acc += __shfl_xor_sync(0xFFFFFFFFu, acc, off);
        if (lane == 0) out[b * 2 + warp] = acc + b2[warp];
    }
}

// ---------------------------------------------------------------------------
extern "C" void kernel_launch(void* const* d_in, const int* in_sizes, int n_in,
                              void* d_out, int out_size) {
    const float* x          = (const float*)d_in[0];
    const float* theta_w    = (const float*)d_in[1];
    const float* theta_b    = (const float*)d_in[2];
    const float* in_proj_w  = (const float*)d_in[3];
    const float* in_proj_b  = (const float*)d_in[4];
    const float* out_proj_w = (const float*)d_in[5];
    const float* out_proj_b = (const float*)d_in[6];
    const float* lng        = (const float*)d_in[7];
    const float* lnb        = (const float*)d_in[8];
    const float* w1         = (const float*)d_in[9];
    const float* b1         = (const float*)d_in[10];
    const float* w2         = (const float*)d_in[11];
    const float* b2         = (const float*)d_in[12];
    float* out = (float*)d_out;

    pre_kernel<<<12, 256>>>(theta_w, theta_b, in_proj_w, in_proj_b,
                            out_proj_w, out_proj_b);
    score_kernel<<<dim3(NS, Bn), 256>>>(x, lng, lnb, w1, b1, w2, b2, out);
}

// round 5
// speedup vs baseline: 3.8631x; 3.8631x over previous
#include <cuda_runtime.h>
#include <math.h>

// GraphTemporalRefiner — folded operators + last-block fused tail.
//   xg = conv7(x);  w[b,n,:] = xl[b]^T W2_n + wb_n   (W2 = Qp_n^T Kp_n/sqrt(HD))
//   scores[b,n,t] = w[b,n] . xg[b,t]  (const cancels in softmax)
//   u[b,n] = softmax-weighted sum_t xg[b,t]
//   a[b]   = C u[b] + ab   (C folds Wv, theta, out_proj);  LN -> gelu MLP -> out
// pre1: P = in_proj_w @ theta  (smem-staged tile GEMM)
// pre2: W2/wb and C/ab from P; resets batch counters
// score: 512 blocks = 16 slices x 32 batches; fused conv + scores + split
//        softmax partials; LAST slice block per batch runs the tail inline.

namespace {
constexpr int Bn  = 32;
constexpr int Tn  = 1024;
constexpr int Dn  = 64;
constexpr int Hn  = 128;
constexpr int NHn = 4;
constexpr int SL  = 64;
constexpr int NS  = Tn / SL;    // 16
}

__device__ float g_P[3 * Hn * Dn];        // Qp | Kp | Vp
__device__ float g_pb[3 * Hn];
__device__ float g_W2[NHn * Dn * Dn];     // (n, e, d)
__device__ float g_wb[NHn * Dn];
__device__ float g_C[Hn * NHn * Dn];      // (i, n*64+d)
__device__ float g_ab[Hn];
__device__ float g_m[Bn * NHn * NS];
__device__ float g_l[Bn * NHn * NS];
__device__ float g_u[Bn * NHn * NS * Dn];
__device__ unsigned int g_cnt[Bn];

// ---------------------------------------------------------------------------
// pre1: P = in_proj_w @ theta_w (384x64), pb = in_proj_w @ theta_b + in_proj_b
// ---------------------------------------------------------------------------
__global__ void __launch_bounds__(256) pre1_kernel(
    const float* __restrict__ theta_w,
    const float* __restrict__ theta_b,
    const float* __restrict__ in_proj_w,
    const float* __restrict__ in_proj_b)
{
    const int tid = threadIdx.x, r0 = blockIdx.x * 16;
    __shared__ float th[Hn * Dn];     // 32 KB
    __shared__ float wr[16 * Hn];     // 8 KB
    __shared__ float tb[Hn];

    for (int i = tid; i < Hn * Dn; i += 256) th[i] = theta_w[i];
    for (int i = tid; i < 16 * Hn; i += 256) wr[i] = in_proj_w[r0 * Hn + i];
    if (tid < Hn) tb[tid] = theta_b[tid];
    __syncthreads();

#pragma unroll
    for (int k = 0; k < 4; k++) {
        int o = tid + k * 256;
        int i = o >> 6, d = o & 63;
        float acc = 0.f;
#pragma unroll 8
        for (int c = 0; c < Hn; c++) acc += wr[i * Hn + c] * th[c * Dn + d];
        g_P[(r0 + i) * Dn + d] = acc;
    }
    if (tid < 16) {
        float acc = in_proj_b[r0 + tid];
#pragma unroll 8
        for (int c = 0; c < Hn; c++) acc += wr[tid * Hn + c] * tb[c];
        g_pb[r0 + tid] = acc;
    }
}

// ---------------------------------------------------------------------------
// pre2: blocks 0..15 -> W2/wb;  blocks 16..31 -> C/ab; block 0 resets g_cnt.
// ---------------------------------------------------------------------------
__global__ void __launch_bounds__(256) pre2_kernel(
    const float* __restrict__ out_proj_w,
    const float* __restrict__ out_proj_b)
{
    const int tid = threadIdx.x;
    const float SCALE = 0.17677669529663687f;   // 1/sqrt(32)

    if (blockIdx.x == 0 && tid < Bn) g_cnt[tid] = 0u;

    if (blockIdx.x < 16) {
        const int n = blockIdx.x >> 2, q = blockIdx.x & 3;
        __shared__ float Qn[32 * Dn];
        __shared__ float Kn[32 * Dn];
        for (int i = tid; i < 32 * Dn; i += 256) {
            Qn[i] = g_P[(n * 32) * Dn + i];
            Kn[i] = g_P[(Hn + n * 32) * Dn + i];
        }
        __syncthreads();
#pragma unroll
        for (int k = 0; k < 4; k++) {
            int o = tid + k * 256;
            int e = q * 16 + (o >> 6), d = o & 63;
            float acc = 0.f;
#pragma unroll 8
            for (int j = 0; j < 32; j++) acc += Qn[j * Dn + e] * Kn[j * Dn + d];
            g_W2[(n * Dn + e) * Dn + d] = acc * SCALE;
        }
        if (q == 0 && tid < Dn) {
            float acc = 0.f;
#pragma unroll 8
            for (int j = 0; j < 32; j++) acc += g_pb[n * 32 + j] * Kn[j * Dn + tid];
            g_wb[n * Dn + tid] = acc * SCALE;
        }
    } else {
        const int chunk = blockIdx.x - 16;        // rows i = chunk*8..+7
        __shared__ float Vp[Hn * Dn];   // 32 KB
        __shared__ float OPs[8 * Hn];   // 4 KB
        __shared__ float vb[Hn];
        for (int i = tid; i < Hn * Dn; i += 256) Vp[i] = g_P[2 * Hn * Dn + i];
        for (int i = tid; i < 8 * Hn; i += 256) OPs[i] = out_proj_w[chunk * 8 * Hn + i];
        if (tid < Hn) vb[tid] = g_pb[2 * Hn + tid];
        __syncthreads();
#pragma unroll
        for (int k = 0; k < 8; k++) {
            int o = tid + k * 256;
            int il = o >> 8, nd = o & 255;
            int n = nd >> 6, d = nd & 63;
            float acc = 0.f;
#pragma unroll 8
            for (int j = 0; j < 32; j++)
                acc += OPs[il * Hn + n * 32 + j] * Vp[(n * 32 + j) * Dn + d];
            g_C[(chunk * 8 + il) * (NHn * Dn) + nd] = acc;
        }
        if (tid < 8) {
            float acc = out_proj_b[chunk * 8 + tid];
#pragma unroll 8
            for (int h = 0; h < Hn; h++) acc += OPs[tid * Hn + h] * vb[h];
            g_ab[chunk * 8 + tid] = acc;
        }
    }
}

// ---------------------------------------------------------------------------
// score: grid (NS, Bn). Fused conv, scores, slice softmax partials.
// Last block per batch runs the full tail inline.
// ---------------------------------------------------------------------------
__global__ void __launch_bounds__(256) score_kernel(
    const float* __restrict__ x,
    const float* __restrict__ ln_g,
    const float* __restrict__ ln_b,
    const float* __restrict__ w1,
    const float* __restrict__ b1,
    const float* __restrict__ w2,
    const float* __restrict__ b2,
    float* __restrict__ out)
{
    const int s = blockIdx.x, b = blockIdx.y, tid = threadIdx.x;
    const int warp = tid >> 5, lane = tid & 31;
    const int t0 = s * SL;

    __shared__ float xr[(SL + 6) * Dn];   // raw x rows [t0-3, t0+SL+2]
    __shared__ float xg[SL][Dn + 1];
    __shared__ float sc[NHn][SL];
    __shared__ float sw[NHn][Dn];
    __shared__ float sxl[Dn];
    __shared__ float s_ML[NHn][2];
    __shared__ float s_u[NHn * Dn];
    __shared__ float s_a[Hn];
    __shared__ float s_hid[Hn];
    __shared__ float s_mv[2];
    __shared__ int   s_last;

    // stage raw x rows (float4, coalesced)
    {
        const float4* xb4 = (const float4*)&x[(size_t)b * Tn * Dn];
        float4* xr4 = (float4*)xr;
        for (int i = tid; i < (SL + 6) * 16; i += 256) {
            int r = i >> 4, gt = t0 - 3 + r;
            if (gt >= 0 && gt < Tn) xr4[i] = __ldg(&xb4[gt * 16 + (i & 15)]);
        }
    }
    // xl = conv at t = T-1 (only backward taps exist)
    if (tid < Dn) {
        float sum = 0.f, ws = 0.f;
#pragma unroll
        for (int dd = 0; dd < 4; dd++) {
            float wv = 1.0f / (1.0f + (float)dd);
            ws += wv;
            sum += wv * __ldg(&x[((size_t)b * Tn + (Tn - 1 - dd)) * Dn + tid]);
        }
        sxl[tid] = __fdividef(sum, ws);
    }
    __syncthreads();

    // w[n][d] = wb + xl^T W2_n  (coalesced over d) — ONCE
    {
        int n = tid >> 6, d = tid & 63;
        float acc = __ldg(&g_wb[tid]);
#pragma unroll 8
        for (int k = 0; k < Dn; k++)
            acc += sxl[k] * __ldg(&g_W2[(n * Dn + k) * Dn + d]);
        sw[n][d] = acc;
    }
    // conv from smem: xg[tl][d]
    for (int o = tid; o < SL * Dn; o += 256) {
        int tl = o >> 6, d = o & 63, t = t0 + tl;
        float sum = 0.f, ws = 0.f;
#pragma unroll
        for (int dd = -3; dd <= 3; dd++) {
            int tt = t + dd;
            if (tt >= 0 && tt < Tn) {
                float wv = 1.0f / (1.0f + (float)(dd < 0 ? -dd : dd));
                ws += wv;
                sum += wv * xr[(tl + 3 + dd) * Dn + d];
            }
        }
        xg[tl][d] = __fdividef(sum, ws);
    }
    __syncthreads();

    // scores: one per thread (n, tl)
    {
        int n = tid >> 6, tl = tid & 63;
        float acc = 0.f;
#pragma unroll 8
        for (int d = 0; d < Dn; d++) acc += sw[n][d] * xg[tl][d];
        sc[n][tl] = acc;
    }
    __syncthreads();

    // slice softmax partials: warp n = head n (64 elems)
    if (tid < NHn * 32) {
        int n = tid >> 5;
        float v0 = sc[n][lane], v1 = sc[n][lane + 32];
        float m = fmaxf(v0, v1);
#pragma unroll
        for (int off = 16; off; off >>= 1)
            m = fmaxf(m, __shfl_xor_sync(0xFFFFFFFFu, m, off));
        float e0 = __expf(v0 - m), e1 = __expf(v1 - m);
        sc[n][lane] = e0; sc[n][lane + 32] = e1;
        float l = e0 + e1;
#pragma unroll
        for (int off = 16; off; off >>= 1)
            l += __shfl_xor_sync(0xFFFFFFFFu, l, off);
        if (lane == 0) {
            g_m[(b * NHn + n) * NS + s] = m;
            g_l[(b * NHn + n) * NS + s] = l;
        }
    }
    __syncthreads();

    // slice u partial
    {
        int n = tid >> 6, d = tid & 63;
        float acc = 0.f;
#pragma unroll 4
        for (int t = 0; t < SL; t++) acc += sc[n][t] * xg[t][d];
        g_u[((b * NHn + n) * NS + s) * Dn + d] = acc;
    }

    // ---- last-block election ----------------------------------------------
    __threadfence();
    __syncthreads();
    if (tid == 0) {
        unsigned int old = atomicAdd(&g_cnt[b], 1u);
        s_last = (old == NS - 1) ? 1 : 0;
    }
    __syncthreads();
    if (!s_last) return;
    __threadfence();

    // ---- tail for batch b ---------------------------------------------------
    if (tid < NHn) {
        float M = -1e30f;
#pragma unroll
        for (int k = 0; k < NS; k++) M = fmaxf(M, g_m[(b * NHn + tid) * NS + k]);
        float L = 0.f;
#pragma unroll
        for (int k = 0; k < NS; k++)
            L += g_l[(b * NHn + tid) * NS + k] *
                 __expf(g_m[(b * NHn + tid) * NS + k] - M);
        s_ML[tid][0] = M;
        s_ML[tid][1] = L;
    }
    __syncthreads();
    {
        int n = tid >> 6, d = tid & 63;
        float acc = 0.f;
#pragma unroll
        for (int k = 0; k < NS; k++)
            acc += g_u[((b * NHn + n) * NS + k) * Dn + d] *
                   __expf(g_m[(b * NHn + n) * NS + k] - s_ML[n][0]);
        s_u[n * Dn + d] = __fdividef(acc, s_ML[n][1]);
    }
    __syncthreads();

    // a[i] = ab[i] + C[i] . u  — warp per output
#pragma unroll
    for (int k = 0; k < 16; k++) {
        int i = warp + 8 * k;
        float acc = 0.f;
#pragma unroll
        for (int m = 0; m < 8; m++)
            acc += __ldg(&g_C[i * 256 + lane + 32 * m]) * s_u[lane + 32 * m];
#pragma unroll
        for (int off = 16; off; off >>= 1)
            acc += __shfl_xor_sync(0xFFFFFFFFu, acc, off);
        if (lane == 0) s_a[i] = acc + g_ab[i];
    }
    __syncthreads();

    // LayerNorm over 128
    if (tid < 32) {
        float sum = s_a[tid] + s_a[tid + 32] + s_a[tid + 64] + s_a[tid + 96];
#pragma unroll
        for (int off = 16; off; off >>= 1)
            sum += __shfl_xor_sync(0xFFFFFFFFu, sum, off);
        if (tid == 0) s_mv[0] = sum * (1.0f / Hn);
    }
    __syncthreads();
    if (tid < 32) {
        float mu = s_mv[0], sum = 0.f;
#pragma unroll
        for (int k = 0; k < 4; k++) {
            float d = s_a[tid + 32 * k] - mu;
            sum += d * d;
        }
#pragma unroll
        for (int off = 16; off; off >>= 1)
            sum += __shfl_xor_sync(0xFFFFFFFFu, sum, off);
        if (tid == 0) s_mv[1] = sum * (1.0f / Hn);
    }
    __syncthreads();
    if (tid < Hn) {
        float inv = rsqrtf(s_mv[1] + 1e-5f);
        s_a[tid] = (s_a[tid] - s_mv[0]) * inv * ln_g[tid] + ln_b[tid];
    }
    __syncthreads();

    // hid = gelu(w1 @ ln + b1)
#pragma unroll
    for (int k = 0; k < 16; k++) {
        int i = warp + 8 * k;
        float acc = 0.f;
#pragma unroll
        for (int m = 0; m < 4; m++)
            acc += __ldg(&w1[i * Hn + lane + 32 * m]) * s_a[lane + 32 * m];
#pragma unroll
        for (int off = 16; off; off >>= 1)
            acc += __shfl_xor_sync(0xFFFFFFFFu, acc, off);
        if (lane == 0) {
            float v = acc + b1[i];
            s_hid[i] = 0.5f * v * (1.0f + erff(v * 0.70710678118654752f));
        }
    }
    __syncthreads();

    if (warp < 2) {
        float acc = 0.f;
#pragma unroll
        for (int m = 0; m < 4; m++)
            acc += __ldg(&w2[warp * Hn + lane + 32 * m]) * s_hid[lane + 32 * m];
#pragma unroll
        for (int off = 16; off; off >>= 1)
            acc += __shfl_xor_sync(0xFFFFFFFFu, acc, off);
        if (lane == 0) out[b * 2 + warp] = acc + b2[warp];
    }
}

// ---------------------------------------------------------------------------
extern "C" void kernel_launch(void* const* d_in, const int* in_sizes, int n_in,
                              void* d_out, int out_size) {
    const float* x          = (const float*)d_in[0];
    const float* theta_w    = (const float*)d_in[1];
    const float* theta_b    = (const float*)d_in[2];
    const float* in_proj_w  = (const float*)d_in[3];
    const float* in_proj_b  = (const float*)d_in[4];
    const float* out_proj_w = (const float*)d_in[5];
    const float* out_proj_b = (const float*)d_in[6];
    const float* lng        = (const float*)d_in[7];
    const float* lnb        = (const float*)d_in[8];
    const float* w1         = (const float*)d_in[9];
    const float* b1         = (const float*)d_in[10];
    const float* w2         = (const float*)d_in[11];
    const float* b2         = (const float*)d_in[12];
    float* out = (float*)d_out;

    pre1_kernel<<<24, 256>>>(theta_w, theta_b, in_proj_w, in_proj_b);
    pre2_kernel<<<32, 256>>>(out_proj_w, out_proj_b);
    score_kernel<<<dim3(NS, Bn), 256>>>(x, lng, lnb, w1, b1, w2, b2, out);
}

// round 6
// speedup vs baseline: 4.1274x; 1.0684x over previous
#include <cuda_runtime.h>
#include <math.h>

// GraphTemporalRefiner — direct per-batch score weights + last-block tail.
//   xg = conv7(x)
//   w[b,n,:]: xl -> g_last -> q -> p -> w (per-batch chain, pre kernel)
//   scores[b,n,t] = w[b,n] . xg[b,t]  (const cancels in softmax)
//   u[b,n] = softmax-weighted sum_t xg[b,t]
//   o = Vp u + vb;  a = out_proj o + b;  LN -> gelu MLP -> out (B,2)
// pre (grid 40): blocks 0..31 per-batch w; blocks 32..39 Vp/vb folding.
// score (grid 16x32): fused conv + scores + split-softmax partials;
//   last slice block per batch runs the whole tail inline.

namespace {
constexpr int Bn  = 32;
constexpr int Tn  = 1024;
constexpr int Dn  = 64;
constexpr int Hn  = 128;
constexpr int NHn = 4;
constexpr int SL  = 64;
constexpr int NS  = Tn / SL;    // 16
}

__device__ float g_w[Bn * NHn * Dn];      // per-batch score weights
__device__ float g_Vp[Hn * Dn];           // Wv @ theta
__device__ float g_vb[Hn];                // Wv @ theta_b + bv
__device__ float g_m[Bn * NHn * NS];
__device__ float g_l[Bn * NHn * NS];
__device__ float g_u[Bn * NHn * NS * Dn];
__device__ unsigned int g_cnt[Bn];

// ---------------------------------------------------------------------------
// pre: blocks 0..31 -> w[b]; blocks 32..39 -> Vp rows (16 each) + vb.
// ---------------------------------------------------------------------------
__global__ void __launch_bounds__(256) pre_kernel(
    const float* __restrict__ x,
    const float* __restrict__ theta_w,    // (128, 64)
    const float* __restrict__ theta_b,
    const float* __restrict__ in_proj_w,  // (384, 128)
    const float* __restrict__ in_proj_b)
{
    const int tid = threadIdx.x;
    const int warp = tid >> 5, lane = tid & 31;
    const float SCALE = 0.17677669529663687f;   // 1/sqrt(32)

    __shared__ float th[Hn * (Dn + 1)];   // padded theta, 33.3 KB

    // stage theta (padded rows: bank-conflict-free for both access patterns)
    for (int i = tid; i < Hn * Dn; i += 256)
        th[(i >> 6) * (Dn + 1) + (i & 63)] = theta_w[i];

    if (blockIdx.x < Bn) {
        const int b = blockIdx.x;
        __shared__ float sxl[Dn];
        __shared__ float s_g[Hn];
        __shared__ float s_q[Hn];
        __shared__ float s_p[NHn][Hn];

        if (tid == 0) g_cnt[b] = 0u;

        // xl = conv at t = T-1 (only backward taps)
        if (tid < Dn) {
            float sum = 0.f, ws = 0.f;
#pragma unroll
            for (int dd = 0; dd < 4; dd++) {
                float wv = 1.0f / (1.0f + (float)dd);
                ws += wv;
                sum += wv * __ldg(&x[((size_t)b * Tn + (Tn - 1 - dd)) * Dn + tid]);
            }
            sxl[tid] = __fdividef(sum, ws);
        }
        __syncthreads();

        // g_last[c] = theta_b[c] + theta[c,:] . xl   (padded smem: no conflicts)
        if (tid < Hn) {
            float acc = theta_b[tid];
#pragma unroll 8
            for (int d = 0; d < Dn; d++) acc += th[tid * (Dn + 1) + d] * sxl[d];
            s_g[tid] = acc;
        }
        __syncthreads();

        // q[i] = bq[i] + Wq[i,:] . g  — warp per output, coalesced
#pragma unroll
        for (int k = 0; k < 16; k++) {
            int i = warp + 8 * k;
            float acc = 0.f;
#pragma unroll
            for (int m = 0; m < 4; m++)
                acc += __ldg(&in_proj_w[i * Hn + lane + 32 * m]) * s_g[lane + 32 * m];
#pragma unroll
            for (int off = 16; off; off >>= 1)
                acc += __shfl_xor_sync(0xFFFFFFFFu, acc, off);
            if (lane == 0) s_q[i] = acc + in_proj_b[i];
        }
        __syncthreads();

        // p[n][c] = sum_j q[n32+j] * Wk[(128+n32+j), c]  — coalesced over c
#pragma unroll
        for (int k = 0; k < 2; k++) {
            int o = tid + k * 256;
            int n = o >> 7, c = o & (Hn - 1);
            float acc = 0.f;
#pragma unroll 8
            for (int j = 0; j < 32; j++)
                acc += s_q[n * 32 + j] * __ldg(&in_proj_w[(Hn + n * 32 + j) * Hn + c]);
            s_p[n][c] = acc;
        }
        __syncthreads();

        // w[n][d] = SCALE * p[n] . theta[:,d]   (padded smem: conflict-free)
        {
            int n = tid >> 6, d = tid & 63;
            float acc = 0.f;
#pragma unroll 8
            for (int c = 0; c < Hn; c++) acc += s_p[n][c] * th[c * (Dn + 1) + d];
            g_w[b * (NHn * Dn) + tid] = acc * SCALE;
        }
    } else {
        // Vp rows r0..r0+15:  Vp[h,d] = Wv[h,:] . theta[:,d]
        const int r0 = (blockIdx.x - Bn) * 16;
        __shared__ float s_wv[16 * Hn];   // 8 KB
        for (int i = tid; i < 16 * Hn; i += 256)
            s_wv[i] = in_proj_w[(2 * Hn + r0) * Hn + i];
        __syncthreads();
#pragma unroll
        for (int k = 0; k < 4; k++) {
            int o = tid + k * 256;        // 1024 = 16*64
            int h = o >> 6, d = o & 63;
            float acc = 0.f;
#pragma unroll 8
            for (int c = 0; c < Hn; c++)
                acc += s_wv[h * Hn + c] * th[c * (Dn + 1) + d];
            g_Vp[(r0 + h) * Dn + d] = acc;
        }
        if (tid < 16) {
            float acc = in_proj_b[2 * Hn + r0 + tid];
#pragma unroll 8
            for (int c = 0; c < Hn; c++)
                acc += s_wv[tid * Hn + c] * theta_b[c];
            g_vb[r0 + tid] = acc;
        }
    }
}

// ---------------------------------------------------------------------------
// score: grid (NS, Bn). Fused conv, scores, slice softmax partials.
// Last block per batch runs the full tail inline.
// ---------------------------------------------------------------------------
__global__ void __launch_bounds__(256) score_kernel(
    const float* __restrict__ x,
    const float* __restrict__ out_proj_w,
    const float* __restrict__ out_proj_b,
    const float* __restrict__ ln_g,
    const float* __restrict__ ln_b,
    const float* __restrict__ w1,
    const float* __restrict__ b1,
    const float* __restrict__ w2,
    const float* __restrict__ b2,
    float* __restrict__ out)
{
    const int s = blockIdx.x, b = blockIdx.y, tid = threadIdx.x;
    const int warp = tid >> 5, lane = tid & 31;
    const int t0 = s * SL;

    __shared__ float xr[(SL + 6) * Dn];   // raw x rows [t0-3, t0+SL+2]
    __shared__ float xg[SL][Dn + 1];
    __shared__ float sc[NHn][SL];
    __shared__ float sw[NHn][Dn];
    __shared__ float s_ML[NHn][2];
    __shared__ float s_u[NHn * Dn];
    __shared__ float s_o[Hn];
    __shared__ float s_a[Hn];
    __shared__ float s_hid[Hn];
    __shared__ float s_mv[2];
    __shared__ int   s_last;

    // stage raw x rows (float4, coalesced) + per-batch score weights
    {
        const float4* xb4 = (const float4*)&x[(size_t)b * Tn * Dn];
        float4* xr4 = (float4*)xr;
        for (int i = tid; i < (SL + 6) * 16; i += 256) {
            int r = i >> 4, gt = t0 - 3 + r;
            if (gt >= 0 && gt < Tn) xr4[i] = __ldg(&xb4[gt * 16 + (i & 15)]);
        }
    }
    sw[tid >> 6][tid & 63] = __ldg(&g_w[b * (NHn * Dn) + tid]);
    __syncthreads();

    // conv from smem: xg[tl][d]
    for (int o = tid; o < SL * Dn; o += 256) {
        int tl = o >> 6, d = o & 63, t = t0 + tl;
        float sum = 0.f, ws = 0.f;
#pragma unroll
        for (int dd = -3; dd <= 3; dd++) {
            int tt = t + dd;
            if (tt >= 0 && tt < Tn) {
                float wv = 1.0f / (1.0f + (float)(dd < 0 ? -dd : dd));
                ws += wv;
                sum += wv * xr[(tl + 3 + dd) * Dn + d];
            }
        }
        xg[tl][d] = __fdividef(sum, ws);
    }
    __syncthreads();

    // scores: one per thread (n, tl)
    {
        int n = tid >> 6, tl = tid & 63;
        float acc = 0.f;
#pragma unroll 8
        for (int d = 0; d < Dn; d++) acc += sw[n][d] * xg[tl][d];
        sc[n][tl] = acc;
    }
    __syncthreads();

    // slice softmax partials: warp n = head n (64 elems)
    if (tid < NHn * 32) {
        int n = tid >> 5;
        float v0 = sc[n][lane], v1 = sc[n][lane + 32];
        float m = fmaxf(v0, v1);
#pragma unroll
        for (int off = 16; off; off >>= 1)
            m = fmaxf(m, __shfl_xor_sync(0xFFFFFFFFu, m, off));
        float e0 = __expf(v0 - m), e1 = __expf(v1 - m);
        sc[n][lane] = e0; sc[n][lane + 32] = e1;
        float l = e0 + e1;
#pragma unroll
        for (int off = 16; off; off >>= 1)
            l += __shfl_xor_sync(0xFFFFFFFFu, l, off);
        if (lane == 0) {
            g_m[(b * NHn + n) * NS + s] = m;
            g_l[(b * NHn + n) * NS + s] = l;
        }
    }
    __syncthreads();

    // slice u partial
    {
        int n = tid >> 6, d = tid & 63;
        float acc = 0.f;
#pragma unroll 4
        for (int t = 0; t < SL; t++) acc += sc[n][t] * xg[t][d];
        g_u[((b * NHn + n) * NS + s) * Dn + d] = acc;
    }

    // ---- last-block election ------------------------------------------------
    __threadfence();
    __syncthreads();
    if (tid == 0) {
        unsigned int old = atomicAdd(&g_cnt[b], 1u);
        s_last = (old == NS - 1) ? 1 : 0;
    }
    __syncthreads();
    if (!s_last) return;
    __threadfence();

    // ---- tail for batch b -----------------------------------------------------
    if (tid < NHn) {
        float M = -1e30f;
#pragma unroll
        for (int k = 0; k < NS; k++) M = fmaxf(M, g_m[(b * NHn + tid) * NS + k]);
        float L = 0.f;
#pragma unroll
        for (int k = 0; k < NS; k++)
            L += g_l[(b * NHn + tid) * NS + k] *
                 __expf(g_m[(b * NHn + tid) * NS + k] - M);
        s_ML[tid][0] = M;
        s_ML[tid][1] = L;
    }
    __syncthreads();
    {
        int n = tid >> 6, d = tid & 63;
        float acc = 0.f;
#pragma unroll
        for (int k = 0; k < NS; k++)
            acc += g_u[((b * NHn + n) * NS + k) * Dn + d] *
                   __expf(g_m[(b * NHn + n) * NS + k] - s_ML[n][0]);
        s_u[n * Dn + d] = __fdividef(acc, s_ML[n][1]);
    }
    __syncthreads();

    // o[i] = vb[i] + Vp[i,:] . u[i/32]  — warp per output, coalesced
#pragma unroll
    for (int k = 0; k < 16; k++) {
        int i = warp + 8 * k;
        int n = i >> 5;
        float acc = 0.f;
#pragma unroll
        for (int m = 0; m < 2; m++)
            acc += __ldg(&g_Vp[i * Dn + lane + 32 * m]) * s_u[n * Dn + lane + 32 * m];
#pragma unroll
        for (int off = 16; off; off >>= 1)
            acc += __shfl_xor_sync(0xFFFFFFFFu, acc, off);
        if (lane == 0) s_o[i] = acc + g_vb[i];
    }
    __syncthreads();

    // a[i] = ob[i] + out_proj[i,:] . o  — warp per output
#pragma unroll
    for (int k = 0; k < 16; k++) {
        int i = warp + 8 * k;
        float acc = 0.f;
#pragma unroll
        for (int m = 0; m < 4; m++)
            acc += __ldg(&out_proj_w[i * Hn + lane + 32 * m]) * s_o[lane + 32 * m];
#pragma unroll
        for (int off = 16; off; off >>= 1)
            acc += __shfl_xor_sync(0xFFFFFFFFu, acc, off);
        if (lane == 0) s_a[i] = acc + out_proj_b[i];
    }
    __syncthreads();

    // LayerNorm over 128
    if (tid < 32) {
        float sum = s_a[tid] + s_a[tid + 32] + s_a[tid + 64] + s_a[tid + 96];
#pragma unroll
        for (int off = 16; off; off >>= 1)
            sum += __shfl_xor_sync(0xFFFFFFFFu, sum, off);
        if (tid == 0) s_mv[0] = sum * (1.0f / Hn);
    }
    __syncthreads();
    if (tid < 32) {
        float mu = s_mv[0], sum = 0.f;
#pragma unroll
        for (int k = 0; k < 4; k++) {
            float d = s_a[tid + 32 * k] - mu;
            sum += d * d;
        }
#pragma unroll
        for (int off = 16; off; off >>= 1)
            sum += __shfl_xor_sync(0xFFFFFFFFu, sum, off);
        if (tid == 0) s_mv[1] = sum * (1.0f / Hn);
    }
    __syncthreads();
    if (tid < Hn) {
        float inv = rsqrtf(s_mv[1] + 1e-5f);
        s_a[tid] = (s_a[tid] - s_mv[0]) * inv * ln_g[tid] + ln_b[tid];
    }
    __syncthreads();

    // hid = gelu(w1 @ ln + b1) — warp per output
#pragma unroll
    for (int k = 0; k < 16; k++) {
        int i = warp + 8 * k;
        float acc = 0.f;
#pragma unroll
        for (int m = 0; m < 4; m++)
            acc += __ldg(&w1[i * Hn + lane + 32 * m]) * s_a[lane + 32 * m];
#pragma unroll
        for (int off = 16; off; off >>= 1)
            acc += __shfl_xor_sync(0xFFFFFFFFu, acc, off);
        if (lane == 0) {
            float v = acc + b1[i];
            s_hid[i] = 0.5f * v * (1.0f + erff(v * 0.70710678118654752f));
        }
    }
    __syncthreads();

    if (warp < 2) {
        float acc = 0.f;
#pragma unroll
        for (int m = 0; m < 4; m++)
            acc += __ldg(&w2[warp * Hn + lane + 32 * m]) * s_hid[lane + 32 * m];
#pragma unroll
        for (int off = 16; off; off >>= 1)
            acc += __shfl_xor_sync(0xFFFFFFFFu, acc, off);
        if (lane == 0) out[b * 2 + warp] = acc + b2[warp];
    }
}

// ---------------------------------------------------------------------------
extern "C" void kernel_launch(void* const* d_in, const int* in_sizes, int n_in,
                              void* d_out, int out_size) {
    const float* x          = (const float*)d_in[0];
    const float* theta_w    = (const float*)d_in[1];
    const float* theta_b    = (const float*)d_in[2];
    const float* in_proj_w  = (const float*)d_in[3];
    const float* in_proj_b  = (const float*)d_in[4];
    const float* out_proj_w = (const float*)d_in[5];
    const float* out_proj_b = (const float*)d_in[6];
    const float* lng        = (const float*)d_in[7];
    const float* lnb        = (const float*)d_in[8];
    const float* w1         = (const float*)d_in[9];
    const float* b1         = (const float*)d_in[10];
    const float* w2         = (const float*)d_in[11];
    const float* b2         = (const float*)d_in[12];
    float* out = (float*)d_out;

    pre_kernel<<<40, 256>>>(x, theta_w, theta_b, in_proj_w, in_proj_b);
    score_kernel<<<dim3(NS, Bn), 256>>>(x, out_proj_w, out_proj_b,
                                        lng, lnb, w1, b1, w2, b2, out);
}